// round 11
// baseline (speedup 1.0000x reference)
#include <cuda_runtime.h>
#include <math_constants.h>

#define VV 96
#define NPOLY 32
#define NPTS 32
#define BATCH 4
#define EPSF 1e-8f
#define THREADS 384   // 12 warps; 3 blocks/SM -> all 384 blocks in ONE wave

// Block = (y, b). Valid polygons compacted. Inside/outside parity is
// precomputed per (poly, x) as a 96-bit mask (crossing test is a threshold
// in u). Hot loop = pure min-d^2 over 16-edge half-poly tasks (2*nv tasks
// over 12 warps for balance); halves merge via smem atomicMin on float bits.
__global__ void __launch_bounds__(THREADS, 3) fused_kernel(
    const float* __restrict__ polygons,    // [B][N][P][2]
    const float* __restrict__ attributes,  // [B][8]
    const float* __restrict__ validity,    // [B][N]
    float* __restrict__ out)               // [B][V][V][V]
{
    const int y = blockIdx.x;
    const int b = blockIdx.y;
    const float py = (float)y * (1.0f / 95.0f);

    __shared__ float4   rec1[NPOLY * NPTS];   // A, B, -ex, -ey   (16 KB)
    __shared__ float2   rec2[NPOLY * NPTS];   // x0, vy           (8 KB)
    __shared__ unsigned skeyU[NPOLY * VV];    // per-poly min d^2 bits (12 KB)
    __shared__ unsigned smask[NPOLY * 3];     // 96-bit parity mask per poly
    __shared__ float    srow[VV];
    __shared__ int      smap[NPOLY];
    __shared__ int      snv;
    __shared__ float    shv;

    const int tid = threadIdx.x;

    // ---- compaction + init ----
    if (tid < 32) {
        float v = validity[b * NPOLY + tid];
        unsigned mask = __ballot_sync(0xffffffffu, v >= 0.5f);
        if (v >= 0.5f) smap[__popc(mask & ((1u << tid) - 1u))] = tid;
        if (tid == 0) snv = __popc(mask);
    }
    if (tid == 32) {
        float a = __saturatef(attributes[b * 8]);
        shv = fminf(fmaxf(rintf(a * (float)VV), 1.0f), (float)VV);
    }
    if (tid < NPOLY * 3) smask[tid] = 0u;
    #pragma unroll
    for (int k = 0; k < (NPOLY * VV) / THREADS; k++)
        skeyU[tid + k * THREADS] = 0x7f800000u;          // +inf
    __syncthreads();

    const int nv = snv;
    const float* pb = polygons + b * (NPOLY * NPTS * 2);

    // ---- per-(valid edge, y) precompute + parity mask build ----
    for (int e = tid; e < nv * NPTS; e += THREADS) {
        int nc = e >> 5, p = e & 31, p1 = (p + 1) & 31;
        int n = smap[nc];
        float x0 = pb[(n * NPTS + p)  * 2 + 0];
        float y0 = pb[(n * NPTS + p)  * 2 + 1];
        float x1 = pb[(n * NPTS + p1) * 2 + 0];
        float y1 = pb[(n * NPTS + p1) * 2 + 1];
        float ex = x1 - x0, ey = y1 - y0;
        float e2 = ex * ex + ey * ey + EPSF;     // ref divisor
        float rx = __fdividef(1.0f, e2);
        float vy = py - y0;
        rec1[e] = make_float4(ex * rx, (vy * ey - x0 * ex) * rx, -ex, -ey);
        rec2[e] = make_float2(x0, vy);

        // crossing threshold: counts for all grid x with u_x < ixm
        bool yc = ((y0 <= py) && (y1 > py)) || ((y1 <= py) && (y0 > py));
        float ix = x0 + ex * ((py - y0) * __fdividef(1.0f, (y1 - y0 + EPSF)));
        float ixm = yc ? ix : -1e30f;
        int c = (int)ceilf(ixm * 95.0f);
        c = max(0, min(96, c));
        // exact boundary fix-up (u_x = x/95, IEEE division as in reference)
        if (c > 0  && !((float)(c - 1) / 95.0f < ixm)) c--;
        if (c > 0  && !((float)(c - 1) / 95.0f < ixm)) c--;
        if (c < 96 &&  ((float)(c    ) / 95.0f < ixm)) c++;
        if (c < 96 &&  ((float)(c    ) / 95.0f < ixm)) c++;
        #pragma unroll
        for (int w = 0; w < 3; w++) {
            int bits = max(0, min(32, c - 32 * w));
            unsigned m = (bits == 32) ? 0xffffffffu : ((1u << bits) - 1u);
            if (m) atomicXor(&smask[nc * 3 + w], m);
        }
    }
    __syncthreads();

    // ---- hot loop: task = (poly, 16-edge half); lane -> 3 x-points ----
    const int warp = tid >> 5, lane = tid & 31;
    const float u0 = (float)(lane     ) * (1.0f / 95.0f);
    const float u1 = (float)(lane + 32) * (1.0f / 95.0f);
    const float u2 = (float)(lane + 64) * (1.0f / 95.0f);

    #pragma unroll 1
    for (int t = warp; t < 2 * nv; t += 12) {
        const int poly = t >> 1;
        const int base = poly * NPTS + (t & 1) * 16;
        float m0 = CUDART_INF_F, m1 = CUDART_INF_F, m2 = CUDART_INF_F;
        #pragma unroll
        for (int p = 0; p < 16; p++) {
            float4 q1 = rec1[base + p];      // broadcast LDS.128
            float2 q2 = rec2[base + p];      // broadcast LDS.64

            float t0 = __saturatef(fmaf(q1.x, u0, q1.y));
            float t1 = __saturatef(fmaf(q1.x, u1, q1.y));
            float t2 = __saturatef(fmaf(q1.x, u2, q1.y));

            float dx0 = fmaf(t0, q1.z, u0 - q2.x);
            float dx1 = fmaf(t1, q1.z, u1 - q2.x);
            float dx2 = fmaf(t2, q1.z, u2 - q2.x);

            float dy0 = fmaf(t0, q1.w, q2.y);
            float dy1 = fmaf(t1, q1.w, q2.y);
            float dy2 = fmaf(t2, q1.w, q2.y);

            m0 = fminf(m0, fmaf(dy0, dy0, dx0 * dx0));
            m1 = fminf(m1, fmaf(dy1, dy1, dx1 * dx1));
            m2 = fminf(m2, fmaf(dy2, dy2, dx2 * dx2));
        }
        // d^2 >= 0: float bits are order-preserving -> uint atomicMin
        atomicMin(&skeyU[poly * VV + lane     ], __float_as_uint(m0));
        atomicMin(&skeyU[poly * VV + lane + 32], __float_as_uint(m1));
        atomicMin(&skeyU[poly * VV + lane + 64], __float_as_uint(m2));
    }
    __syncthreads();

    // ---- combine polys (sign from mask), sqrt + sigmoid once per point ----
    if (tid < VV) {
        const int w = tid >> 5, bit = tid & 31;
        float kmin = CUDART_INF_F;
        for (int n = 0; n < nv; n++) {
            float m = __uint_as_float(skeyU[n * VV + tid]);
            bool inside = (smask[n * 3 + w] >> bit) & 1u;
            kmin = fminf(kmin, inside ? -m : m);
        }
        float d   = sqrtf(fabsf(kmin));
        float sdf = (kmin < 0.0f) ? -d : d;
        // sigmoid(-100*sdf); kmin==+inf (no valid poly) -> mask 0, matches ref
        srow[tid] = __fdividef(1.0f, 1.0f + __expf(100.0f * sdf));
    }
    __syncthreads();

    // ---- extrude: write 96 z-slices of this (b, y) row ----
    const float hv = shv;
    const float4* row4 = (const float4*)srow;
    float4* out4 = (float4*)out;
    const int obase = (b * VV) * VV * (VV / 4) + y * (VV / 4);
    #pragma unroll
    for (int k = 0; k < 6; k++) {
        int idx = tid + k * THREADS;           // 2304 float4s total
        int z = idx / (VV / 4);
        int x4 = idx - z * (VV / 4);
        float4 c = row4[x4];
        if ((float)z >= hv) c = make_float4(0.f, 0.f, 0.f, 0.f);
        out4[obase + z * VV * (VV / 4) + x4] = c;
    }
}

extern "C" void kernel_launch(void* const* d_in, const int* in_sizes, int n_in,
                              void* d_out, int out_size) {
    const float* polygons   = (const float*)d_in[0];
    const float* attributes = (const float*)d_in[1];
    const float* validity   = (const float*)d_in[2];

    dim3 grid(VV, BATCH);
    fused_kernel<<<grid, THREADS>>>(polygons, attributes, validity, (float*)d_out);
}

// round 14
// speedup vs baseline: 1.0342x; 1.0342x over previous
#include <cuda_runtime.h>
#include <math_constants.h>

#define VV 96
#define NPOLY 32
#define NPTS 32
#define BATCH 4
#define EPSF 1e-8f
#define THREADS 384   // 12 warps; 3 blocks/SM -> all 384 blocks in ONE wave

// Block = (y, b). Valid polygons compacted. Inside/outside parity precomputed
// per (poly, x) as a 96-bit mask (crossing test is a threshold in u).
// Hot loop = pure min-d^2 over WHOLE polygons (min over all 32 edges completes
// in-register BEFORE the mask sign is applied -- the R12 half-task fold applied
// sign per half, which corrupts inside points). Signed keys fold across polys
// in registers; one 12-way smem combine at the end.
__global__ void __launch_bounds__(THREADS, 3) fused_kernel(
    const float* __restrict__ polygons,    // [B][N][P][2]
    const float* __restrict__ attributes,  // [B][8]
    const float* __restrict__ validity,    // [B][N]
    float* __restrict__ out)               // [B][V][V][V]
{
    const int y = blockIdx.x;
    const int b = blockIdx.y;
    const float py = (float)y * (1.0f / 95.0f);

    __shared__ float4   rec1[NPOLY * NPTS];   // A, B, -ex, -ey   (16 KB)
    __shared__ float2   rec2[NPOLY * NPTS];   // x0, vy           (8 KB)
    __shared__ unsigned smask[NPOLY * 3];     // 96-bit inside mask per poly
    __shared__ float    skey[12][VV];         // per-warp running keys
    __shared__ float    srow[VV];
    __shared__ int      smap[NPOLY];
    __shared__ int      snv;
    __shared__ float    shv;

    const int tid = threadIdx.x;

    // ---- compaction + init ----
    if (tid < 32) {
        float v = validity[b * NPOLY + tid];
        unsigned mask = __ballot_sync(0xffffffffu, v >= 0.5f);
        if (v >= 0.5f) smap[__popc(mask & ((1u << tid) - 1u))] = tid;
        if (tid == 0) snv = __popc(mask);
    }
    if (tid == 32) {
        float a = __saturatef(attributes[b * 8]);
        shv = fminf(fmaxf(rintf(a * (float)VV), 1.0f), (float)VV);
    }
    if (tid < NPOLY * 3) smask[tid] = 0u;
    __syncthreads();

    const int nv = snv;
    const float* pb = polygons + b * (NPOLY * NPTS * 2);

    // ---- per-(valid edge, y) precompute + parity mask build ----
    for (int e = tid; e < nv * NPTS; e += THREADS) {
        int nc = e >> 5, p = e & 31, p1 = (p + 1) & 31;
        int n = smap[nc];
        float x0 = pb[(n * NPTS + p)  * 2 + 0];
        float y0 = pb[(n * NPTS + p)  * 2 + 1];
        float x1 = pb[(n * NPTS + p1) * 2 + 0];
        float y1 = pb[(n * NPTS + p1) * 2 + 1];
        float ex = x1 - x0, ey = y1 - y0;
        float e2 = ex * ex + ey * ey + EPSF;     // ref divisor
        float rx = __fdividef(1.0f, e2);
        float vy = py - y0;
        rec1[e] = make_float4(ex * rx, (vy * ey - x0 * ex) * rx, -ex, -ey);
        rec2[e] = make_float2(x0, vy);

        // crossing counts for all grid x with u_x < ixm  (threshold in u)
        bool yc = ((y0 <= py) && (y1 > py)) || ((y1 <= py) && (y0 > py));
        float ix = x0 + ex * ((py - y0) * __fdividef(1.0f, (y1 - y0 + EPSF)));
        float ixm = yc ? ix : -1e30f;
        int c = (int)ceilf(ixm * 95.0f);
        c = max(0, min(96, c));
        // exact boundary fix-up against IEEE u_x = x/95 (verified bit-exact R11)
        if (c > 0  && !((float)(c - 1) / 95.0f < ixm)) c--;
        if (c > 0  && !((float)(c - 1) / 95.0f < ixm)) c--;
        if (c < 96 &&  ((float)(c    ) / 95.0f < ixm)) c++;
        if (c < 96 &&  ((float)(c    ) / 95.0f < ixm)) c++;
        #pragma unroll
        for (int w = 0; w < 3; w++) {
            int bits = max(0, min(32, c - 32 * w));
            unsigned m = (bits == 32) ? 0xffffffffu : ((1u << bits) - 1u);
            if (m) atomicXor(&smask[nc * 3 + w], m);
        }
    }
    __syncthreads();

    // ---- hot loop: warp -> whole polys (warp, warp+12, ...); 3 x/lane ----
    const int warp = tid >> 5, lane = tid & 31;
    const float u0 = (float)(lane     ) * (1.0f / 95.0f);
    const float u1 = (float)(lane + 32) * (1.0f / 95.0f);
    const float u2 = (float)(lane + 64) * (1.0f / 95.0f);

    float key0 = CUDART_INF_F, key1 = CUDART_INF_F, key2 = CUDART_INF_F;

    #pragma unroll 1
    for (int n = warp; n < nv; n += 12) {
        float m0 = CUDART_INF_F, m1 = CUDART_INF_F, m2 = CUDART_INF_F;
        #pragma unroll
        for (int p = 0; p < NPTS; p++) {
            float4 q1 = rec1[n * NPTS + p];  // broadcast LDS.128
            float2 q2 = rec2[n * NPTS + p];  // broadcast LDS.64

            float t0 = __saturatef(fmaf(q1.x, u0, q1.y));
            float t1 = __saturatef(fmaf(q1.x, u1, q1.y));
            float t2 = __saturatef(fmaf(q1.x, u2, q1.y));

            float dx0 = fmaf(t0, q1.z, u0 - q2.x);
            float dx1 = fmaf(t1, q1.z, u1 - q2.x);
            float dx2 = fmaf(t2, q1.z, u2 - q2.x);

            float dy0 = fmaf(t0, q1.w, q2.y);
            float dy1 = fmaf(t1, q1.w, q2.y);
            float dy2 = fmaf(t2, q1.w, q2.y);

            m0 = fminf(m0, fmaf(dy0, dy0, dx0 * dx0));
            m1 = fminf(m1, fmaf(dy1, dy1, dx1 * dx1));
            m2 = fminf(m2, fmaf(dy2, dy2, dx2 * dx2));
        }
        // per-poly min complete -> now apply this poly's inside sign
        unsigned w0 = smask[n * 3 + 0];
        unsigned w1 = smask[n * 3 + 1];
        unsigned w2 = smask[n * 3 + 2];
        float k0 = ((w0 >> lane) & 1u) ? -m0 : m0;
        float k1 = ((w1 >> lane) & 1u) ? -m1 : m1;
        float k2 = ((w2 >> lane) & 1u) ? -m2 : m2;
        key0 = fminf(key0, k0);
        key1 = fminf(key1, k1);
        key2 = fminf(key2, k2);
    }
    skey[warp][lane     ] = key0;
    skey[warp][lane + 32] = key1;
    skey[warp][lane + 64] = key2;
    __syncthreads();

    // ---- combine 12 warps, sqrt + sigmoid once per point ----
    if (tid < VV) {
        float k = skey[0][tid];
        #pragma unroll
        for (int w = 1; w < 12; w++) k = fminf(k, skey[w][tid]);
        float d   = sqrtf(fabsf(k));
        float sdf = (k < 0.0f) ? -d : d;
        // sigmoid(-100*sdf); k==+inf (no valid poly) -> mask 0, matches ref
        srow[tid] = __fdividef(1.0f, 1.0f + __expf(100.0f * sdf));
    }
    __syncthreads();

    // ---- extrude: write 96 z-slices of this (b, y) row ----
    const float hv = shv;
    const float4* row4 = (const float4*)srow;
    float4* out4 = (float4*)out;
    const int obase = (b * VV) * VV * (VV / 4) + y * (VV / 4);
    #pragma unroll
    for (int k = 0; k < 6; k++) {
        int idx = tid + k * THREADS;           // 2304 float4s total
        int z = idx / (VV / 4);
        int x4 = idx - z * (VV / 4);
        float4 c = row4[x4];
        if ((float)z >= hv) c = make_float4(0.f, 0.f, 0.f, 0.f);
        out4[obase + z * VV * (VV / 4) + x4] = c;
    }
}

extern "C" void kernel_launch(void* const* d_in, const int* in_sizes, int n_in,
                              void* d_out, int out_size) {
    const float* polygons   = (const float*)d_in[0];
    const float* attributes = (const float*)d_in[1];
    const float* validity   = (const float*)d_in[2];

    dim3 grid(VV, BATCH);
    fused_kernel<<<grid, THREADS>>>(polygons, attributes, validity, (float*)d_out);
}